// round 15
// baseline (speedup 1.0000x reference)
#include <cuda_runtime.h>
#include <cuda_bf16.h>
#include <math.h>

// ---------------- problem constants ----------------
#define NB 4096
#define ND 128
#define NT2 64                 // 64-row tiles
#define NPAIR2 2080
#define INV_TEMP 14.285714285714285714f          // 1/0.07
#define KE 20.609929155556619f                   // INV_TEMP * log2(e)
#define LN2 0.69314718055994531f

// ---------------- device scratch (no allocs) ----------------
__device__ float g_Rp[2][8][NB];                  // partial row-max per pool tile
__device__ float g_RfM[NB];
__device__ float g_RsM[NB];
__device__ unsigned g_baseBits[32768];            // [256 rows][128 words]
__device__ float g_part[NT2][NB * 6];             // [slot][row*6+q]
__device__ float g_sum[NB * 6];
__device__ __nv_bfloat16 g_bf[4][2][NB * ND];     // [stage][hi/lo][elem]
__device__ __nv_bfloat16 g_bfp[2][2][1024 * ND];  // pools [mat][hi/lo]

// ---------------- helpers ----------------
__device__ __forceinline__ float ex2f(float x) {
    float r; asm("ex2.approx.ftz.f32 %0, %1;" : "=f"(r) : "f"(x)); return r;
}
__device__ __forceinline__ float lg2f(float x) {
    float r; asm("lg2.approx.ftz.f32 %0, %1;" : "=f"(r) : "f"(x)); return r;
}
__device__ __forceinline__ unsigned smem_u32(const void* p) {
    return (unsigned)__cvta_generic_to_shared(p);
}

#define CP_ASYNC16(dst, src) asm volatile("cp.async.cg.shared.global [%0], [%1], 16;" :: "r"(dst), "l"(src))
#define CP_COMMIT() asm volatile("cp.async.commit_group;" ::: "memory")
#define CP_WAIT1() asm volatile("cp.async.wait_group 1;" ::: "memory")
#define CP_WAIT0() asm volatile("cp.async.wait_group 0;" ::: "memory")

__device__ __forceinline__ void ldsm4(unsigned& r0, unsigned& r1, unsigned& r2,
                                      unsigned& r3, unsigned addr) {
    asm volatile("ldmatrix.sync.aligned.m8n8.x4.shared.b16 {%0,%1,%2,%3}, [%4];"
                 : "=r"(r0), "=r"(r1), "=r"(r2), "=r"(r3) : "r"(addr));
}
__device__ __forceinline__ void mma_bf16(float* d, const unsigned* a, const unsigned* b) {
    asm volatile("mma.sync.aligned.m16n8k16.row.col.f32.bf16.bf16.f32 "
                 "{%0,%1,%2,%3}, {%4,%5,%6,%7}, {%8,%9}, {%0,%1,%2,%3};"
                 : "+f"(d[0]), "+f"(d[1]), "+f"(d[2]), "+f"(d[3])
                 : "r"(a[0]), "r"(a[1]), "r"(a[2]), "r"(a[3]),
                   "r"(b[0]), "r"(b[1]));
}

// ---------------- fused prep: split-bf16 conversions + mask pack ----------------
__global__ void prep_kernel(const float* __restrict__ z, const float* __restrict__ spr,
                            const float* __restrict__ f, const float* __restrict__ zmix,
                            const float* __restrict__ pag, const float* __restrict__ psp,
                            const float* __restrict__ base) {
    int i = blockIdx.x * 256 + threadIdx.x;     // 524288 threads
    const float* srcs[4] = {f, spr, z, zmix};
#pragma unroll
    for (int m = 0; m < 4; m++) {
        float x = srcs[m][i];
        __nv_bfloat16 hi = __float2bfloat16(x);
        __nv_bfloat16 lo = __float2bfloat16(x - __bfloat162float(hi));
        g_bf[m][0][i] = hi;
        g_bf[m][1][i] = lo;
    }
    if (i < 131072) {
        const float* ps[2] = {pag, psp};
#pragma unroll
        for (int m = 0; m < 2; m++) {
            float x = ps[m][i];
            __nv_bfloat16 hi = __float2bfloat16(x);
            __nv_bfloat16 lo = __float2bfloat16(x - __bfloat162float(hi));
            g_bfp[m][0][i] = hi;
            g_bfp[m][1][i] = lo;
        }
    }
    if (i < 32768) {
        const float* p = base + (size_t)i * 32;
        unsigned bits = 0;
#pragma unroll
        for (int b = 0; b < 32; b++) bits |= (p[b] > 0.f) ? (1u << b) : 0u;
        g_baseBits[i] = bits;
    }
}

// ---------------- rmax kernel: tensor path (proven round-13/14 code) ----------------
#define TILE_B 18432u          // 128 rows x 144B pitch
#define BUF_STRIDE 73728u      // 4 tiles

__device__ __forceinline__ void load_tile(unsigned sdst,
                                          const __nv_bfloat16* __restrict__ src,
                                          int row0, int h, int tid, int nthr) {
#pragma unroll
    for (int idx = tid; idx < 1024; idx += nthr) {
        int r = idx >> 3, cc = idx & 7;
        CP_ASYNC16(sdst + r * 144 + cc * 16,
                   src + (size_t)(row0 + r) * ND + h * 64 + cc * 8);
    }
}

__device__ __forceinline__ void mma_k16_step8(float* acc, unsigned ta_hi, unsigned ta_lo,
                                              unsigned tb_hi, unsigned tb_lo,
                                              unsigned aoff, unsigned boff, int ks) {
    unsigned ah[4], al[4];
    ldsm4(ah[0], ah[1], ah[2], ah[3], ta_hi + aoff + ks * 32);
    ldsm4(al[0], al[1], al[2], al[3], ta_lo + aoff + ks * 32);
#pragma unroll
    for (int np = 0; np < 8; np++) {
        unsigned bh[4], bl[4];
        ldsm4(bh[0], bh[1], bh[2], bh[3], tb_hi + np * 2304u + boff + ks * 32);
        ldsm4(bl[0], bl[1], bl[2], bl[3], tb_lo + np * 2304u + boff + ks * 32);
        float* d = acc + np * 8;
        mma_bf16(d,     ah, bh);
        mma_bf16(d + 4, ah, bh + 2);
        mma_bf16(d,     ah, bl);
        mma_bf16(d + 4, ah, bl + 2);
        mma_bf16(d,     al, bh);
        mma_bf16(d + 4, al, bh + 2);
    }
}

__global__ void __launch_bounds__(256, 1)
rmax2_kernel() {
    extern __shared__ char smc[];
    unsigned sb = smem_u32(smc);
    int tid = threadIdx.x;
    int w = tid >> 5, l = tid & 31;
    int g0 = blockIdx.x * 128, p0 = blockIdx.y * 128, mat = blockIdx.z;
    int rA = 16 * w + (l >> 2), rB = rA + 8;

    const __nv_bfloat16* Ahi = &g_bf[mat][0][0];
    const __nv_bfloat16* Alo = &g_bf[mat][1][0];
    const __nv_bfloat16* Bhi = &g_bfp[mat][0][0];
    const __nv_bfloat16* Blo = &g_bfp[mat][1][0];

#pragma unroll
    for (int c = 0; c < 2; c++) {
        unsigned bs = sb + c * BUF_STRIDE;
        load_tile(bs,              Ahi, g0, c, tid, 256);
        load_tile(bs + TILE_B,     Alo, g0, c, tid, 256);
        load_tile(bs + 2 * TILE_B, Bhi, p0, c, tid, 256);
        load_tile(bs + 3 * TILE_B, Blo, p0, c, tid, 256);
        CP_COMMIT();
    }

    unsigned aoff = (unsigned)((16 * w + (l & 15)) * 144 + ((l & 16) ? 16 : 0));
    unsigned boff = (unsigned)(((l & 7) + ((l & 16) ? 8 : 0)) * 144 + ((l & 8) ? 16 : 0));

    float acc[64];
#pragma unroll
    for (int i = 0; i < 64; i++) acc[i] = 0.f;
#pragma unroll
    for (int c = 0; c < 2; c++) {
        if (c == 0) { CP_WAIT1(); } else { CP_WAIT0(); }
        __syncthreads();
        unsigned bufb = sb + (unsigned)c * BUF_STRIDE;
#pragma unroll
        for (int ks = 0; ks < 4; ks++)
            mma_k16_step8(acc, bufb, bufb + TILE_B,
                          bufb + 2 * TILE_B, bufb + 3 * TILE_B, aoff, boff, ks);
    }

    float mxA = -1e30f, mxB = -1e30f;
#pragma unroll
    for (int t2 = 0; t2 < 16; t2++) {
        mxA = fmaxf(mxA, fmaxf(acc[t2 * 4], acc[t2 * 4 + 1]));
        mxB = fmaxf(mxB, fmaxf(acc[t2 * 4 + 2], acc[t2 * 4 + 3]));
    }
#pragma unroll
    for (int off = 1; off < 4; off <<= 1) {
        mxA = fmaxf(mxA, __shfl_xor_sync(0xffffffffu, mxA, off));
        mxB = fmaxf(mxB, __shfl_xor_sync(0xffffffffu, mxB, off));
    }
    if ((l & 3) == 0) {
        g_Rp[mat][blockIdx.y][g0 + rA] = mxA;
        g_Rp[mat][blockIdx.y][g0 + rB] = mxB;
    }
}

__global__ void merge2_kernel() {
    int i = blockIdx.x * 256 + threadIdx.x;
    float mf = -1e30f, ms = -1e30f;
#pragma unroll
    for (int p = 0; p < 8; p++) {
        mf = fmaxf(mf, g_Rp[0][p][i]);
        ms = fmaxf(ms, g_Rp[1][p][i]);
    }
    g_RfM[i] = mf;
    g_RsM[i] = ms;
}

// ---------------- pair kernel: 64x64 symmetric pairs, 2 blocks/SM ----------------
// 8 warps; warp (wr = w>>1, wc = w&1) owns rows 16wr..16wr+15 x cols 32wc..32wc+31.
// acc[16] per thread (2 n16-groups x 8), masks u16.
#define TILE64 9216u           // 64 rows x 144B pitch
#define BUF64 36864u           // 4 tiles
#define OFF_COLR 73728         // 128 floats
#define OFF_BB   74240         // 128 u32
#define OFF_TB   74752         // 128 u32
#define OFF_CSUM 75264         // [4 wr][6 q][64 cols] = 6144 B
#define OFF_RSUM 81408         // [2 wc][64 rows][6] = 3072 B
#define SMEM_PAIR64 84480

__device__ __forceinline__ void load_tile64(unsigned sdst,
                                            const __nv_bfloat16* __restrict__ src,
                                            int row0, int h, int tid) {
#pragma unroll
    for (int idx = tid; idx < 512; idx += 256) {
        int r = idx >> 3, cc = idx & 7;
        CP_ASYNC16(sdst + r * 144 + cc * 16,
                   src + (size_t)(row0 + r) * ND + h * 64 + cc * 8);
    }
}

__device__ __forceinline__ void mma_k16_step2(float* acc, unsigned ta_hi, unsigned ta_lo,
                                              unsigned tb_hi, unsigned tb_lo,
                                              unsigned aoff, unsigned boff, int ks) {
    unsigned ah[4], al[4];
    ldsm4(ah[0], ah[1], ah[2], ah[3], ta_hi + aoff + ks * 32);
    ldsm4(al[0], al[1], al[2], al[3], ta_lo + aoff + ks * 32);
#pragma unroll
    for (int np = 0; np < 2; np++) {
        unsigned bh[4], bl[4];
        ldsm4(bh[0], bh[1], bh[2], bh[3], tb_hi + np * 2304u + boff + ks * 32);
        ldsm4(bl[0], bl[1], bl[2], bl[3], tb_lo + np * 2304u + boff + ks * 32);
        float* d = acc + np * 8;
        mma_bf16(d,     ah, bh);
        mma_bf16(d + 4, ah, bh + 2);
        mma_bf16(d,     ah, bl);
        mma_bf16(d + 4, ah, bl + 2);
        mma_bf16(d,     al, bh);
        mma_bf16(d + 4, al, bh + 2);
    }
}

__global__ void __launch_bounds__(256, 2)
pair_kernel() {
    extern __shared__ char smc[];
    unsigned sb = smem_u32(smc);
    float* smf = (float*)smc;
    float* colRf = smf + OFF_COLR / 4;
    float* colRs = colRf + 64;
    unsigned* bbr = (unsigned*)(smc + OFF_BB);
    unsigned* tbt = (unsigned*)(smc + OFF_TB);
    float* csum = smf + OFF_CSUM / 4;
    float* rsum = smf + OFF_RSUM / 4;

    int tid = threadIdx.x;
    int w = tid >> 5, l = tid & 31;
    int wr = w >> 1, wc = w & 1;
    int cb = wc * 32;

    int pi = blockIdx.x, a = 0;
    while (pi >= NT2 - a) { pi -= NT2 - a; a++; }
    int b = a + pi;
    int g0 = a * 64, j0 = b * 64;

    int rA = 16 * wr + (l >> 2), rB = rA + 8;

    if (tid < 64) {
        colRf[tid] = g_RfM[j0 + tid];
        colRs[tid] = g_RsM[j0 + tid];
        const unsigned* srcR = &g_baseBits[((g0 + tid) & 255) * 128 + (j0 >> 5)];
        const unsigned* srcT = &g_baseBits[((j0 + tid) & 255) * 128 + (g0 >> 5)];
        bbr[tid * 2 + 0] = srcR[0];
        bbr[tid * 2 + 1] = srcR[1];
        tbt[tid * 2 + 0] = srcT[0];
        tbt[tid * 2 + 1] = srcT[1];
    }

    // prologue: chunks 0,1 of stage f
#pragma unroll
    for (int c0 = 0; c0 < 2; c0++) {
        unsigned bs = sb + (unsigned)c0 * BUF64;
        load_tile64(bs,             &g_bf[0][0][0], g0, c0, tid);
        load_tile64(bs + TILE64,    &g_bf[0][1][0], g0, c0, tid);
        load_tile64(bs + 2 * TILE64, &g_bf[0][0][0], j0, c0, tid);
        load_tile64(bs + 3 * TILE64, &g_bf[0][1][0], j0, c0, tid);
        CP_COMMIT();
    }

    unsigned aoff = (unsigned)((16 * wr + (l & 15)) * 144 + ((l & 16) ? 16 : 0));
    unsigned boff = (unsigned)((cb + (l & 7) + ((l & 16) ? 8 : 0)) * 144 +
                               ((l & 8) ? 16 : 0));

    float RfA = g_RfM[g0 + rA], RfB = g_RfM[g0 + rB];
    float RsA = g_RsM[g0 + rA], RsB = g_RsM[g0 + rB];

    unsigned keep = 0xFFFFu;
    if (a == b) {
#pragma unroll
        for (int np = 0; np < 2; np++)
#pragma unroll
            for (int j = 0; j < 8; j++) {
                int col = cb + np * 16 + ((j & 4) ? 8 : 0) + 2 * (l & 3) + (j & 1);
                int row = (j & 2) ? rB : rA;
                if (col == row) keep &= ~(1u << (np * 8 + j));
            }
    }

    float acc[16];
    unsigned bA = 0, bE = 0, bN = 0, bNT = 0;
    float SzA = 0.f, SzB = 0.f, ZzA = 0.f, ZzB = 0.f;
    float SmA = 0.f, SmB = 0.f, ZmA = 0.f, ZmB = 0.f;

    for (int c = 0; c < 8; c++) {
        if (c < 7) { CP_WAIT1(); } else { CP_WAIT0(); }
        __syncthreads();
        if ((c & 1) == 0) {
#pragma unroll
            for (int i = 0; i < 16; i++) acc[i] = 0.f;
        }
        unsigned bufb = sb + (unsigned)(c & 1) * BUF64;
#pragma unroll
        for (int ks = 0; ks < 4; ks++)
            mma_k16_step2(acc, bufb, bufb + TILE64,
                          bufb + 2 * TILE64, bufb + 3 * TILE64, aoff, boff, ks);

        if (c == 1) {
            // ---- f masks: bA, bN, bNT ----
            unsigned wA2[2] = {bbr[rA * 2], bbr[rA * 2 + 1]};
            unsigned wB2[2] = {bbr[rB * 2], bbr[rB * 2 + 1]};
            unsigned m1 = 0, ng = 0, ngT = 0;
#pragma unroll
            for (int np = 0; np < 2; np++)
#pragma unroll
                for (int j = 0; j < 8; j++) {
                    int idx = np * 8 + j;
                    float v = acc[idx];
                    int col = cb + np * 16 + ((j & 4) ? 8 : 0) + 2 * (l & 3) + (j & 1);
                    float Rr = (j & 2) ? RfB : RfA;
                    if ((Rr < v) | (colRf[col] < v)) m1 |= 1u << idx;
                    unsigned word = (j & 2) ? wB2[col >> 5] : wA2[col >> 5];
                    if ((word >> (col & 31)) & 1u) ng |= 1u << idx;
                    int rr = (j & 2) ? rB : rA;
                    if ((tbt[col * 2 + (rr >> 5)] >> (rr & 31)) & 1u) ngT |= 1u << idx;
                }
            bA = m1 & keep;
            bN = bA | (ng & keep);
            bNT = bA | (ngT & keep);
        } else if (c == 3) {
            // ---- s masks: bE ----
            unsigned m2 = 0;
#pragma unroll
            for (int np = 0; np < 2; np++)
#pragma unroll
                for (int j = 0; j < 8; j++) {
                    int idx = np * 8 + j;
                    float v = acc[idx];
                    int col = cb + np * 16 + ((j & 4) ? 8 : 0) + 2 * (l & 3) + (j & 1);
                    float Rr = (j & 2) ? RsB : RsA;
                    if ((Rr < v) | (colRs[col] < v)) m2 |= 1u << idx;
                }
            bE = m2 & keep;
            // ---- col-side counts ----
            if (a != b) {
#pragma unroll
                for (int np = 0; np < 2; np++)
#pragma unroll
                    for (int jc = 0; jc < 4; jc++) {
                        int j0i = (jc & 1) | ((jc & 2) << 1);   // 0,1,4,5
                        int i1 = np * 8 + j0i, i2 = i1 + 2;
                        float wAs = (((bA >> i1) & 1u) ? 1.f : 0.f) +
                                    (((bA >> i2) & 1u) ? 1.f : 0.f);
                        float wEs = (((bE >> i1) & 1u) ? 1.f : 0.f) +
                                    (((bE >> i2) & 1u) ? 1.f : 0.f);
                        float cw = wAs + 0.5f * wEs, cv = wAs;
#pragma unroll
                        for (int off = 4; off < 32; off <<= 1) {
                            cw += __shfl_xor_sync(0xffffffffu, cw, off);
                            cv += __shfl_xor_sync(0xffffffffu, cv, off);
                        }
                        if (l < 4) {
                            int col = cb + np * 16 + ((j0i & 4) ? 8 : 0) + 2 * l + (j0i & 1);
                            csum[wr * 384 + 4 * 64 + col] = cw;
                            csum[wr * 384 + 5 * 64 + col] = cv;
                        }
                    }
            }
        } else if (c == 5 || c == 7) {
            // ---- logit epilogue: row side ----
            float sA = 0.f, sB = 0.f, zA = 0.f, zB = 0.f;
#pragma unroll
            for (int np = 0; np < 2; np++)
#pragma unroll
                for (int j = 0; j < 8; j++) {
                    int idx = np * 8 + j;
                    float v = acc[idx];
                    float wgt = (((bA >> idx) & 1u) ? 1.0f : 0.0f) +
                                (((bE >> idx) & 1u) ? 0.5f : 0.0f);
                    float e = ex2f(KE * (v - 1.0f));
                    float za = ((bN >> idx) & 1u) ? e : 0.f;
                    if (j & 2) { sB += wgt * v; zB += za; }
                    else       { sA += wgt * v; zA += za; }
                }
            if (c == 5) { SzA = sA; SzB = sB; ZzA = zA; ZzB = zB; }
            else        { SmA = sA; SmB = sB; ZmA = zA; ZmB = zB; }
            // ---- col side ----
            if (a != b) {
                int q0 = (c == 5) ? 0 : 2;
#pragma unroll
                for (int np = 0; np < 2; np++)
#pragma unroll
                    for (int jc = 0; jc < 4; jc++) {
                        int j0i = (jc & 1) | ((jc & 2) << 1);
                        int i1 = np * 8 + j0i, i2 = i1 + 2;
                        float v1 = acc[i1], v2 = acc[i2];
                        float w1 = (((bA >> i1) & 1u) ? 1.0f : 0.0f) +
                                   (((bE >> i1) & 1u) ? 0.5f : 0.0f);
                        float w2 = (((bA >> i2) & 1u) ? 1.0f : 0.0f) +
                                   (((bE >> i2) & 1u) ? 0.5f : 0.0f);
                        float sv = w1 * v1 + w2 * v2;
                        float e1 = ex2f(KE * (v1 - 1.0f));
                        float e2 = ex2f(KE * (v2 - 1.0f));
                        float ze = (((bNT >> i1) & 1u) ? e1 : 0.f) +
                                   (((bNT >> i2) & 1u) ? e2 : 0.f);
#pragma unroll
                        for (int off = 4; off < 32; off <<= 1) {
                            sv += __shfl_xor_sync(0xffffffffu, sv, off);
                            ze += __shfl_xor_sync(0xffffffffu, ze, off);
                        }
                        if (l < 4) {
                            int col = cb + np * 16 + ((j0i & 4) ? 8 : 0) + 2 * l + (j0i & 1);
                            csum[wr * 384 + q0 * 64 + col] = ze;
                            csum[wr * 384 + (q0 + 1) * 64 + col] = sv;
                        }
                    }
            }
        }

        __syncthreads();
        if (c + 2 < 8) {
            int cc = c + 2;
            const __nv_bfloat16* hi = &g_bf[cc >> 1][0][0];
            const __nv_bfloat16* lo = &g_bf[cc >> 1][1][0];
            int h = cc & 1;
            unsigned bn = sb + (unsigned)(c & 1) * BUF64;
            load_tile64(bn,              hi, g0, h, tid);
            load_tile64(bn + TILE64,     lo, g0, h, tid);
            load_tile64(bn + 2 * TILE64, hi, j0, h, tid);
            load_tile64(bn + 3 * TILE64, lo, j0, h, tid);
            CP_COMMIT();
        }
    }

    // ---- row-side: reduce over lane cols, write per-col-half partials ----
    float pAa = (float)__popc(bA & 0x3333u);
    float pAb = (float)__popc(bA & 0xCCCCu);
    float pEa = (float)__popc(bE & 0x3333u);
    float pEb = (float)__popc(bE & 0xCCCCu);
    float qA[6] = {ZzA, ZmA, SzA, SmA, pAa + 0.5f * pEa, pAa};
    float qB[6] = {ZzB, ZmB, SzB, SmB, pAb + 0.5f * pEb, pAb};
#pragma unroll
    for (int q = 0; q < 6; q++) {
#pragma unroll
        for (int off = 1; off < 4; off <<= 1) {
            qA[q] += __shfl_xor_sync(0xffffffffu, qA[q], off);
            qB[q] += __shfl_xor_sync(0xffffffffu, qB[q], off);
        }
    }
    if ((l & 3) == 0) {
#pragma unroll
        for (int q = 0; q < 6; q++) {
            rsum[(wc * 64 + rA) * 6 + q] = qA[q];
            rsum[(wc * 64 + rB) * 6 + q] = qB[q];
        }
    }
    __syncthreads();
    if (tid < 64) {
        float* d = &g_part[b][(size_t)(g0 + tid) * 6];
#pragma unroll
        for (int q = 0; q < 6; q++)
            d[q] = rsum[tid * 6 + q] + rsum[(64 + tid) * 6 + q];
    }

    // ---- col-side write ----
    if (a != b && tid >= 64 && tid < 128) {
        int colx = tid - 64;
        float s[6] = {0.f, 0.f, 0.f, 0.f, 0.f, 0.f};
#pragma unroll
        for (int w4 = 0; w4 < 4; w4++)
#pragma unroll
            for (int q = 0; q < 6; q++) s[q] += csum[w4 * 384 + q * 64 + colx];
        float* d = &g_part[a][(size_t)(j0 + colx) * 6];
        d[0] = s[0];   // Zz
        d[1] = s[2];   // Zm
        d[2] = s[1];   // Sz
        d[3] = s[3];   // Sm
        d[4] = s[4];   // ws
        d[5] = s[5];   // vc
    }
}

// ---------------- slot sum + final reduction ----------------
__global__ void slotsum_kernel() {
    int i = blockIdx.x * 256 + threadIdx.x;
    float s = 0.f;
    for (int sl = 0; sl < NT2; sl++) s += g_part[sl][i];
    g_sum[i] = s;
}

__global__ void reduce_kernel(float* __restrict__ out) {
    __shared__ float s1[256], s2[256];
    int tid = threadIdx.x;
    float grand = 0.f;
    for (int m = 0; m < 16; m++) {
        int i = m * 256 + tid;
        float q[6];
#pragma unroll
        for (int qn = 0; qn < 6; qn++) q[qn] = g_sum[(size_t)i * 6 + qn];
        float Zz = q[0], Zm = q[1], Sz = q[2], Sm = q[3], ww = q[4], vcc = q[5];
        float num = 0.f, den = 0.f;
        if (vcc > 0.5f) {
            float lzz = INV_TEMP + LN2 * lg2f(Zz);
            float lzm = INV_TEMP + LN2 * lg2f(Zm);
            num = INV_TEMP * (Sz + Sm) - ww * (lzz + lzm);
            den = ww;
        }
        s1[tid] = num;
        s2[tid] = den;
        __syncthreads();
        for (int off = 128; off > 0; off >>= 1) {
            if (tid < off) { s1[tid] += s1[tid + off]; s2[tid] += s2[tid + off]; }
            __syncthreads();
        }
        if (tid == 0 && s2[0] != 0.f) grand += s1[0] / s2[0];
        __syncthreads();
    }
    if (tid == 0) out[0] = -grand / 32.0f;   // /M/2 with M=16
}

// ---------------- launch ----------------
extern "C" void kernel_launch(void* const* d_in, const int* in_sizes, int n_in,
                              void* d_out, int out_size) {
    const float* z    = (const float*)d_in[0];
    const float* spr  = (const float*)d_in[1];
    const float* f    = (const float*)d_in[2];
    const float* pag  = (const float*)d_in[3];
    const float* psp  = (const float*)d_in[4];
    const float* zmix = (const float*)d_in[5];
    const float* base = (const float*)d_in[6];
    float* out = (float*)d_out;

    const int SMEM_RMAX = 2 * BUF_STRIDE;     // 147456
    cudaFuncSetAttribute(rmax2_kernel, cudaFuncAttributeMaxDynamicSharedMemorySize, SMEM_RMAX);
    cudaFuncSetAttribute(pair_kernel, cudaFuncAttributeMaxDynamicSharedMemorySize, SMEM_PAIR64);

    prep_kernel<<<2048, 256>>>(z, spr, f, zmix, pag, psp, base);
    rmax2_kernel<<<dim3(32, 8, 2), 256, SMEM_RMAX>>>();
    merge2_kernel<<<16, 256>>>();
    pair_kernel<<<NPAIR2, 256, SMEM_PAIR64>>>();
    slotsum_kernel<<<96, 256>>>();
    reduce_kernel<<<1, 256>>>(out);
}

// round 17
// speedup vs baseline: 1.4503x; 1.4503x over previous
#include <cuda_runtime.h>
#include <cuda_fp16.h>
#include <math.h>

// ---------------- problem constants ----------------
#define NB 4096
#define ND 128
#define NT2 64                 // 64-row tiles
#define NPAIR2 2080
#define INV_TEMP 14.285714285714285714f          // 1/0.07
#define KE 20.609929155556619f                   // INV_TEMP * log2(e)
#define LN2 0.69314718055994531f

// ---------------- device scratch (no allocs) ----------------
__device__ float g_Rp[2][8][NB];                  // partial row-max per pool tile
__device__ float g_RfM[NB];
__device__ float g_RsM[NB];
__device__ unsigned g_baseBits[32768];            // [256 rows][128 words]
__device__ float g_part[NT2][NB * 6];             // [slot][row*6+q]
__device__ float g_sum[NB * 6];
__device__ __half g_hf[4][NB * ND];               // [stage] fp16 single
__device__ __half g_hfp[2][1024 * ND];            // pools fp16

// ---------------- helpers ----------------
__device__ __forceinline__ float ex2f(float x) {
    float r; asm("ex2.approx.ftz.f32 %0, %1;" : "=f"(r) : "f"(x)); return r;
}
__device__ __forceinline__ float lg2f(float x) {
    float r; asm("lg2.approx.ftz.f32 %0, %1;" : "=f"(r) : "f"(x)); return r;
}
__device__ __forceinline__ unsigned smem_u32(const void* p) {
    return (unsigned)__cvta_generic_to_shared(p);
}

#define CP_ASYNC16(dst, src) asm volatile("cp.async.cg.shared.global [%0], [%1], 16;" :: "r"(dst), "l"(src))
#define CP_COMMIT() asm volatile("cp.async.commit_group;" ::: "memory")
#define CP_WAIT1() asm volatile("cp.async.wait_group 1;" ::: "memory")
#define CP_WAIT0() asm volatile("cp.async.wait_group 0;" ::: "memory")

__device__ __forceinline__ void ldsm4(unsigned& r0, unsigned& r1, unsigned& r2,
                                      unsigned& r3, unsigned addr) {
    asm volatile("ldmatrix.sync.aligned.m8n8.x4.shared.b16 {%0,%1,%2,%3}, [%4];"
                 : "=r"(r0), "=r"(r1), "=r"(r2), "=r"(r3) : "r"(addr));
}
__device__ __forceinline__ void mma_fp16(float* d, const unsigned* a, const unsigned* b) {
    asm volatile("mma.sync.aligned.m16n8k16.row.col.f32.f16.f16.f32 "
                 "{%0,%1,%2,%3}, {%4,%5,%6,%7}, {%8,%9}, {%0,%1,%2,%3};"
                 : "+f"(d[0]), "+f"(d[1]), "+f"(d[2]), "+f"(d[3])
                 : "r"(a[0]), "r"(a[1]), "r"(a[2]), "r"(a[3]),
                   "r"(b[0]), "r"(b[1]));
}

// ---------------- fused prep: fp16 conversion + mask pack ----------------
__global__ void prep_kernel(const float* __restrict__ z, const float* __restrict__ spr,
                            const float* __restrict__ f, const float* __restrict__ zmix,
                            const float* __restrict__ pag, const float* __restrict__ psp,
                            const float* __restrict__ base) {
    int i = blockIdx.x * 256 + threadIdx.x;     // 524288 threads
    const float* srcs[4] = {f, spr, z, zmix};
#pragma unroll
    for (int m = 0; m < 4; m++) g_hf[m][i] = __float2half_rn(srcs[m][i]);
    if (i < 131072) {
        g_hfp[0][i] = __float2half_rn(pag[i]);
        g_hfp[1][i] = __float2half_rn(psp[i]);
    }
    if (i < 32768) {
        const float* p = base + (size_t)i * 32;
        unsigned bits = 0;
#pragma unroll
        for (int b = 0; b < 32; b++) bits |= (p[b] > 0.f) ? (1u << b) : 0u;
        g_baseBits[i] = bits;
    }
}

// ---------------- tile loaders ----------------
#define TILE_B 18432u          // 128 rows x 144B pitch
#define BUFR 36864u            // A + B tiles (128-row)

__device__ __forceinline__ void load_tile(unsigned sdst,
                                          const __half* __restrict__ src,
                                          int row0, int h, int tid, int nthr) {
#pragma unroll
    for (int idx = tid; idx < 1024; idx += nthr) {
        int r = idx >> 3, cc = idx & 7;
        CP_ASYNC16(sdst + r * 144 + cc * 16,
                   src + (size_t)(row0 + r) * ND + h * 64 + cc * 8);
    }
}

// single-combo k16 step over 8 n-pairs (128-col B tile)
__device__ __forceinline__ void mma_k16_s8(float* acc, unsigned ta, unsigned tb,
                                           unsigned aoff, unsigned boff, int ks) {
    unsigned ah[4];
    ldsm4(ah[0], ah[1], ah[2], ah[3], ta + aoff + ks * 32);
#pragma unroll
    for (int np = 0; np < 8; np++) {
        unsigned bh[4];
        ldsm4(bh[0], bh[1], bh[2], bh[3], tb + np * 2304u + boff + ks * 32);
        mma_fp16(acc + np * 8,     ah, bh);
        mma_fp16(acc + np * 8 + 4, ah, bh + 2);
    }
}

// ---------------- rmax kernel: tensor path, fp16 single ----------------
__global__ void __launch_bounds__(256, 1)
rmax2_kernel() {
    extern __shared__ char smc[];
    unsigned sb = smem_u32(smc);
    int tid = threadIdx.x;
    int w = tid >> 5, l = tid & 31;
    int g0 = blockIdx.x * 128, p0 = blockIdx.y * 128, mat = blockIdx.z;
    int rA = 16 * w + (l >> 2), rB = rA + 8;

    const __half* A = &g_hf[mat][0];
    const __half* B = &g_hfp[mat][0];

#pragma unroll
    for (int c = 0; c < 2; c++) {
        unsigned bs = sb + c * BUFR;
        load_tile(bs,          A, g0, c, tid, 256);
        load_tile(bs + TILE_B, B, p0, c, tid, 256);
        CP_COMMIT();
    }

    unsigned aoff = (unsigned)((16 * w + (l & 15)) * 144 + ((l & 16) ? 16 : 0));
    unsigned boff = (unsigned)(((l & 7) + ((l & 16) ? 8 : 0)) * 144 + ((l & 8) ? 16 : 0));

    float acc[64];
#pragma unroll
    for (int i = 0; i < 64; i++) acc[i] = 0.f;
#pragma unroll
    for (int c = 0; c < 2; c++) {
        if (c == 0) { CP_WAIT1(); } else { CP_WAIT0(); }
        __syncthreads();
        unsigned bufb = sb + (unsigned)c * BUFR;
#pragma unroll
        for (int ks = 0; ks < 4; ks++)
            mma_k16_s8(acc, bufb, bufb + TILE_B, aoff, boff, ks);
    }

    float mxA = -1e30f, mxB = -1e30f;
#pragma unroll
    for (int t2 = 0; t2 < 16; t2++) {
        mxA = fmaxf(mxA, fmaxf(acc[t2 * 4], acc[t2 * 4 + 1]));
        mxB = fmaxf(mxB, fmaxf(acc[t2 * 4 + 2], acc[t2 * 4 + 3]));
    }
#pragma unroll
    for (int off = 1; off < 4; off <<= 1) {
        mxA = fmaxf(mxA, __shfl_xor_sync(0xffffffffu, mxA, off));
        mxB = fmaxf(mxB, __shfl_xor_sync(0xffffffffu, mxB, off));
    }
    if ((l & 3) == 0) {
        g_Rp[mat][blockIdx.y][g0 + rA] = mxA;
        g_Rp[mat][blockIdx.y][g0 + rB] = mxB;
    }
}

__global__ void merge2_kernel() {
    int i = blockIdx.x * 256 + threadIdx.x;
    float mf = -1e30f, ms = -1e30f;
#pragma unroll
    for (int p = 0; p < 8; p++) {
        mf = fmaxf(mf, g_Rp[0][p][i]);
        ms = fmaxf(ms, g_Rp[1][p][i]);
    }
    g_RfM[i] = mf;
    g_RsM[i] = ms;
}

// ---------------- pair kernel: 64x64 symmetric pairs, fp16 single ----------------
// 8 warps; warp (wr = w>>1, wc = w&1) owns rows 16wr..16wr+15 x cols 32wc..32wc+31.
#define TILE64 9216u           // 64 rows x 144B pitch
#define BUF64 18432u           // A + B tiles
#define OFF_COLR 36864         // 128 floats
#define OFF_BB   37376         // 128 u32
#define OFF_TB   37888         // 128 u32
#define OFF_CSUM 38400         // [4 wr][6 q][64 cols] = 6144 B
#define OFF_RSUM 44544         // [2 wc][64 rows][6] = 3072 B
#define SMEM_PAIR64 47616

__device__ __forceinline__ void load_tile64(unsigned sdst,
                                            const __half* __restrict__ src,
                                            int row0, int h, int tid) {
#pragma unroll
    for (int idx = tid; idx < 512; idx += 256) {
        int r = idx >> 3, cc = idx & 7;
        CP_ASYNC16(sdst + r * 144 + cc * 16,
                   src + (size_t)(row0 + r) * ND + h * 64 + cc * 8);
    }
}

__device__ __forceinline__ void mma_k16_s2(float* acc, unsigned ta, unsigned tb,
                                           unsigned aoff, unsigned boff, int ks) {
    unsigned ah[4];
    ldsm4(ah[0], ah[1], ah[2], ah[3], ta + aoff + ks * 32);
#pragma unroll
    for (int np = 0; np < 2; np++) {
        unsigned bh[4];
        ldsm4(bh[0], bh[1], bh[2], bh[3], tb + np * 2304u + boff + ks * 32);
        mma_fp16(acc + np * 8,     ah, bh);
        mma_fp16(acc + np * 8 + 4, ah, bh + 2);
    }
}

__global__ void __launch_bounds__(256, 2)
pair_kernel() {
    extern __shared__ char smc[];
    unsigned sb = smem_u32(smc);
    float* smf = (float*)smc;
    float* colRf = smf + OFF_COLR / 4;
    float* colRs = colRf + 64;
    unsigned* bbr = (unsigned*)(smc + OFF_BB);
    unsigned* tbt = (unsigned*)(smc + OFF_TB);
    float* csum = smf + OFF_CSUM / 4;
    float* rsum = smf + OFF_RSUM / 4;

    int tid = threadIdx.x;
    int w = tid >> 5, l = tid & 31;
    int wr = w >> 1, wc = w & 1;
    int cb = wc * 32;

    int pi = blockIdx.x, a = 0;
    while (pi >= NT2 - a) { pi -= NT2 - a; a++; }
    int b = a + pi;
    int g0 = a * 64, j0 = b * 64;

    int rA = 16 * wr + (l >> 2), rB = rA + 8;

    if (tid < 64) {
        colRf[tid] = g_RfM[j0 + tid];
        colRs[tid] = g_RsM[j0 + tid];
        const unsigned* srcR = &g_baseBits[((g0 + tid) & 255) * 128 + (j0 >> 5)];
        const unsigned* srcT = &g_baseBits[((j0 + tid) & 255) * 128 + (g0 >> 5)];
        bbr[tid * 2 + 0] = srcR[0];
        bbr[tid * 2 + 1] = srcR[1];
        tbt[tid * 2 + 0] = srcT[0];
        tbt[tid * 2 + 1] = srcT[1];
    }

    // prologue: chunks 0,1 of stage f
#pragma unroll
    for (int c0 = 0; c0 < 2; c0++) {
        unsigned bs = sb + (unsigned)c0 * BUF64;
        load_tile64(bs,          &g_hf[0][0], g0, c0, tid);
        load_tile64(bs + TILE64, &g_hf[0][0], j0, c0, tid);
        CP_COMMIT();
    }

    unsigned aoff = (unsigned)((16 * wr + (l & 15)) * 144 + ((l & 16) ? 16 : 0));
    unsigned boff = (unsigned)((cb + (l & 7) + ((l & 16) ? 8 : 0)) * 144 +
                               ((l & 8) ? 16 : 0));

    float RfA = g_RfM[g0 + rA], RfB = g_RfM[g0 + rB];
    float RsA = g_RsM[g0 + rA], RsB = g_RsM[g0 + rB];

    unsigned keep = 0xFFFFu;
    if (a == b) {
#pragma unroll
        for (int np = 0; np < 2; np++)
#pragma unroll
            for (int j = 0; j < 8; j++) {
                int col = cb + np * 16 + ((j & 4) ? 8 : 0) + 2 * (l & 3) + (j & 1);
                int row = (j & 2) ? rB : rA;
                if (col == row) keep &= ~(1u << (np * 8 + j));
            }
    }

    float acc[16];
    unsigned bA = 0, bE = 0, bN = 0, bNT = 0;
    float SzA = 0.f, SzB = 0.f, ZzA = 0.f, ZzB = 0.f;
    float SmA = 0.f, SmB = 0.f, ZmA = 0.f, ZmB = 0.f;

    for (int c = 0; c < 8; c++) {
        if (c < 7) { CP_WAIT1(); } else { CP_WAIT0(); }
        __syncthreads();
        if ((c & 1) == 0) {
#pragma unroll
            for (int i = 0; i < 16; i++) acc[i] = 0.f;
        }
        unsigned bufb = sb + (unsigned)(c & 1) * BUF64;
#pragma unroll
        for (int ks = 0; ks < 4; ks++)
            mma_k16_s2(acc, bufb, bufb + TILE64, aoff, boff, ks);

        if (c == 1) {
            // ---- f masks: bA, bN, bNT ----
            unsigned wA2[2] = {bbr[rA * 2], bbr[rA * 2 + 1]};
            unsigned wB2[2] = {bbr[rB * 2], bbr[rB * 2 + 1]};
            unsigned m1 = 0, ng = 0, ngT = 0;
#pragma unroll
            for (int np = 0; np < 2; np++)
#pragma unroll
                for (int j = 0; j < 8; j++) {
                    int idx = np * 8 + j;
                    float v = acc[idx];
                    int col = cb + np * 16 + ((j & 4) ? 8 : 0) + 2 * (l & 3) + (j & 1);
                    float Rr = (j & 2) ? RfB : RfA;
                    if ((Rr < v) | (colRf[col] < v)) m1 |= 1u << idx;
                    unsigned word = (j & 2) ? wB2[col >> 5] : wA2[col >> 5];
                    if ((word >> (col & 31)) & 1u) ng |= 1u << idx;
                    int rr = (j & 2) ? rB : rA;
                    if ((tbt[col * 2 + (rr >> 5)] >> (rr & 31)) & 1u) ngT |= 1u << idx;
                }
            bA = m1 & keep;
            bN = bA | (ng & keep);
            bNT = bA | (ngT & keep);
        } else if (c == 3) {
            // ---- s masks: bE ----
            unsigned m2 = 0;
#pragma unroll
            for (int np = 0; np < 2; np++)
#pragma unroll
                for (int j = 0; j < 8; j++) {
                    int idx = np * 8 + j;
                    float v = acc[idx];
                    int col = cb + np * 16 + ((j & 4) ? 8 : 0) + 2 * (l & 3) + (j & 1);
                    float Rr = (j & 2) ? RsB : RsA;
                    if ((Rr < v) | (colRs[col] < v)) m2 |= 1u << idx;
                }
            bE = m2 & keep;
            // ---- col-side counts ----
            if (a != b) {
#pragma unroll
                for (int np = 0; np < 2; np++)
#pragma unroll
                    for (int jc = 0; jc < 4; jc++) {
                        int j0i = (jc & 1) | ((jc & 2) << 1);   // 0,1,4,5
                        int i1 = np * 8 + j0i, i2 = i1 + 2;
                        float wAs = (((bA >> i1) & 1u) ? 1.f : 0.f) +
                                    (((bA >> i2) & 1u) ? 1.f : 0.f);
                        float wEs = (((bE >> i1) & 1u) ? 1.f : 0.f) +
                                    (((bE >> i2) & 1u) ? 1.f : 0.f);
                        float cw = wAs + 0.5f * wEs, cv = wAs;
#pragma unroll
                        for (int off = 4; off < 32; off <<= 1) {
                            cw += __shfl_xor_sync(0xffffffffu, cw, off);
                            cv += __shfl_xor_sync(0xffffffffu, cv, off);
                        }
                        if (l < 4) {
                            int col = cb + np * 16 + ((j0i & 4) ? 8 : 0) + 2 * l + (j0i & 1);
                            csum[wr * 384 + 4 * 64 + col] = cw;
                            csum[wr * 384 + 5 * 64 + col] = cv;
                        }
                    }
            }
        } else if (c == 5 || c == 7) {
            // ---- logit epilogue: row side ----
            float sA = 0.f, sB = 0.f, zA = 0.f, zB = 0.f;
#pragma unroll
            for (int np = 0; np < 2; np++)
#pragma unroll
                for (int j = 0; j < 8; j++) {
                    int idx = np * 8 + j;
                    float v = acc[idx];
                    float wgt = (((bA >> idx) & 1u) ? 1.0f : 0.0f) +
                                (((bE >> idx) & 1u) ? 0.5f : 0.0f);
                    float e = ex2f(KE * (v - 1.0f));
                    float za = ((bN >> idx) & 1u) ? e : 0.f;
                    if (j & 2) { sB += wgt * v; zB += za; }
                    else       { sA += wgt * v; zA += za; }
                }
            if (c == 5) { SzA = sA; SzB = sB; ZzA = zA; ZzB = zB; }
            else        { SmA = sA; SmB = sB; ZmA = zA; ZmB = zB; }
            // ---- col side ----
            if (a != b) {
                int q0 = (c == 5) ? 0 : 2;
#pragma unroll
                for (int np = 0; np < 2; np++)
#pragma unroll
                    for (int jc = 0; jc < 4; jc++) {
                        int j0i = (jc & 1) | ((jc & 2) << 1);
                        int i1 = np * 8 + j0i, i2 = i1 + 2;
                        float v1 = acc[i1], v2 = acc[i2];
                        float w1 = (((bA >> i1) & 1u) ? 1.0f : 0.0f) +
                                   (((bE >> i1) & 1u) ? 0.5f : 0.0f);
                        float w2 = (((bA >> i2) & 1u) ? 1.0f : 0.0f) +
                                   (((bE >> i2) & 1u) ? 0.5f : 0.0f);
                        float sv = w1 * v1 + w2 * v2;
                        float e1 = ex2f(KE * (v1 - 1.0f));
                        float e2 = ex2f(KE * (v2 - 1.0f));
                        float ze = (((bNT >> i1) & 1u) ? e1 : 0.f) +
                                   (((bNT >> i2) & 1u) ? e2 : 0.f);
#pragma unroll
                        for (int off = 4; off < 32; off <<= 1) {
                            sv += __shfl_xor_sync(0xffffffffu, sv, off);
                            ze += __shfl_xor_sync(0xffffffffu, ze, off);
                        }
                        if (l < 4) {
                            int col = cb + np * 16 + ((j0i & 4) ? 8 : 0) + 2 * l + (j0i & 1);
                            csum[wr * 384 + q0 * 64 + col] = ze;
                            csum[wr * 384 + (q0 + 1) * 64 + col] = sv;
                        }
                    }
            }
        }

        __syncthreads();
        if (c + 2 < 8) {
            int cc = c + 2;
            const __half* src = &g_hf[cc >> 1][0];
            int h = cc & 1;
            unsigned bn = sb + (unsigned)(c & 1) * BUF64;
            load_tile64(bn,          src, g0, h, tid);
            load_tile64(bn + TILE64, src, j0, h, tid);
            CP_COMMIT();
        }
    }

    // ---- row-side: reduce over lane cols, write per-col-half partials ----
    float pAa = (float)__popc(bA & 0x3333u);
    float pAb = (float)__popc(bA & 0xCCCCu);
    float pEa = (float)__popc(bE & 0x3333u);
    float pEb = (float)__popc(bE & 0xCCCCu);
    float qA[6] = {ZzA, ZmA, SzA, SmA, pAa + 0.5f * pEa, pAa};
    float qB[6] = {ZzB, ZmB, SzB, SmB, pAb + 0.5f * pEb, pAb};
#pragma unroll
    for (int q = 0; q < 6; q++) {
#pragma unroll
        for (int off = 1; off < 4; off <<= 1) {
            qA[q] += __shfl_xor_sync(0xffffffffu, qA[q], off);
            qB[q] += __shfl_xor_sync(0xffffffffu, qB[q], off);
        }
    }
    if ((l & 3) == 0) {
#pragma unroll
        for (int q = 0; q < 6; q++) {
            rsum[(wc * 64 + rA) * 6 + q] = qA[q];
            rsum[(wc * 64 + rB) * 6 + q] = qB[q];
        }
    }
    __syncthreads();
    if (tid < 64) {
        float* d = &g_part[b][(size_t)(g0 + tid) * 6];
#pragma unroll
        for (int q = 0; q < 6; q++)
            d[q] = rsum[tid * 6 + q] + rsum[(64 + tid) * 6 + q];
    }

    // ---- col-side write ----
    if (a != b && tid >= 64 && tid < 128) {
        int colx = tid - 64;
        float s[6] = {0.f, 0.f, 0.f, 0.f, 0.f, 0.f};
#pragma unroll
        for (int w4 = 0; w4 < 4; w4++)
#pragma unroll
            for (int q = 0; q < 6; q++) s[q] += csum[w4 * 384 + q * 64 + colx];
        float* d = &g_part[a][(size_t)(j0 + colx) * 6];
        d[0] = s[0];   // Zz
        d[1] = s[2];   // Zm
        d[2] = s[1];   // Sz
        d[3] = s[3];   // Sm
        d[4] = s[4];   // ws
        d[5] = s[5];   // vc
    }
}

// ---------------- slot sum + final reduction ----------------
__global__ void slotsum_kernel() {
    int i = blockIdx.x * 256 + threadIdx.x;
    float s = 0.f;
    for (int sl = 0; sl < NT2; sl++) s += g_part[sl][i];
    g_sum[i] = s;
}

__global__ void reduce_kernel(float* __restrict__ out) {
    __shared__ float s1[256], s2[256];
    int tid = threadIdx.x;
    float grand = 0.f;
    for (int m = 0; m < 16; m++) {
        int i = m * 256 + tid;
        float q[6];
#pragma unroll
        for (int qn = 0; qn < 6; qn++) q[qn] = g_sum[(size_t)i * 6 + qn];
        float Zz = q[0], Zm = q[1], Sz = q[2], Sm = q[3], ww = q[4], vcc = q[5];
        float num = 0.f, den = 0.f;
        if (vcc > 0.5f) {
            float lzz = INV_TEMP + LN2 * lg2f(Zz);
            float lzm = INV_TEMP + LN2 * lg2f(Zm);
            num = INV_TEMP * (Sz + Sm) - ww * (lzz + lzm);
            den = ww;
        }
        s1[tid] = num;
        s2[tid] = den;
        __syncthreads();
        for (int off = 128; off > 0; off >>= 1) {
            if (tid < off) { s1[tid] += s1[tid + off]; s2[tid] += s2[tid + off]; }
            __syncthreads();
        }
        if (tid == 0 && s2[0] != 0.f) grand += s1[0] / s2[0];
        __syncthreads();
    }
    if (tid == 0) out[0] = -grand / 32.0f;   // /M/2 with M=16
}

// ---------------- launch ----------------
extern "C" void kernel_launch(void* const* d_in, const int* in_sizes, int n_in,
                              void* d_out, int out_size) {
    const float* z    = (const float*)d_in[0];
    const float* spr  = (const float*)d_in[1];
    const float* f    = (const float*)d_in[2];
    const float* pag  = (const float*)d_in[3];
    const float* psp  = (const float*)d_in[4];
    const float* zmix = (const float*)d_in[5];
    const float* base = (const float*)d_in[6];
    float* out = (float*)d_out;

    const int SMEM_RMAX = 2 * BUFR;           // 73728
    cudaFuncSetAttribute(rmax2_kernel, cudaFuncAttributeMaxDynamicSharedMemorySize, SMEM_RMAX);
    cudaFuncSetAttribute(pair_kernel, cudaFuncAttributeMaxDynamicSharedMemorySize, SMEM_PAIR64);

    prep_kernel<<<2048, 256>>>(z, spr, f, zmix, pag, psp, base);
    rmax2_kernel<<<dim3(32, 8, 2), 256, SMEM_RMAX>>>();
    merge2_kernel<<<16, 256>>>();
    pair_kernel<<<NPAIR2, 256, SMEM_PAIR64>>>();
    slotsum_kernel<<<96, 256>>>();
    reduce_kernel<<<1, 256>>>(out);
}